// round 14
// baseline (speedup 1.0000x reference)
#include <cuda_runtime.h>
#include <math.h>

// Problem constants
#define NBATCH   64
#define NCH      128
#define NPTS     256           // 16x16 image grid
#define MAPS     32            // BEV map size
#define NCELLS   (MAPS*MAPS)   // 1024
#define HMAXV    14
#define GROUPS   16            // channel groups per batch
#define CH_PER   (NCH / GROUPS)   // 8
#define NTILES   (NBATCH * GROUPS) // 1024
#define NBLOCKB  512               // kernel B blocks (2 tiles each, single wave)
#define MAXEXTRA 256
#define NBMW     (NCELLS / 32)     // 32 bitmap words per batch

// Scratch (static __device__ globals — no dynamic allocation)
__device__ int      g_win[NBATCH * NCELLS];        // packed (y<<8)|tid, -1 = empty
__device__ unsigned g_bitmap[NBATCH * NBMW];       // per-cell "has extra contributor"
__device__ int      g_ecnt[NBATCH];
__device__ int      g_extras[NBATCH * MAXEXTRA];   // packed (cell<<8)|tid

// ---------------- Kernel A: per-batch winner map + extras (64 blocks) ----------------
__global__ __launch_bounds__(256)
void winner_kernel(const float* __restrict__ depth,      // (64,1,256)
                   const float* __restrict__ cam)        // (3,256)
{
    __shared__ __align__(16) int win[NCELLS];
    __shared__ unsigned sbm[NBMW];
    __shared__ int sdup;

    const int tid = threadIdx.x;        // 0..255 == point id
    const int b   = blockIdx.x;         // batch
    const int cl4 = tid * 4;

    // issue loads first
    const float d  = depth[b * NPTS + tid];
    const float cx = cam[          tid];
    const float cy = cam[  NPTS  + tid];
    const float cz = cam[2*NPTS  + tid];

    *reinterpret_cast<int4*>(&win[cl4]) = make_int4(-1, -1, -1, -1);
    if (tid < NBMW) sbm[tid] = 0u;
    if (tid == 0) sdup = 0;

    // ---- per-point voxel index math (bit-exact vs JAX float32) ----
    const float px = __fmul_rn(d, cx);
    const float py = __fadd_rn(__fmul_rn(d, cy), 1.72f);   // + CAM_HEIGHT
    const float pz = __fmul_rn(d, cz);

    const float CELLF = 0.1f;  // float32(3.2/32)
    const int xi = (int)floorf(__fdiv_rn(px, CELLF)) + (MAPS / 2);
    const int yi = (int)floorf(__fdiv_rn(py, CELLF));
    const int zi = (int)floorf(__fdiv_rn(pz, CELLF)) + MAPS;

    const bool valid = (xi >= 0) & (xi < MAPS) & (zi >= 0) & (zi < MAPS) & (yi < HMAXV);

    // replicate reference flat index semantics: flat = (z*32+x)*14 + y
    int cell = -1, ye = -1;
    if (valid) {
        const int vflat = (zi * MAPS + xi) * HMAXV + yi;
        if (vflat >= 0) {
            cell = vflat / HMAXV;           // ye in [0,13]
            ye   = vflat - cell * HMAXV;
        }
    }
    __syncthreads();   // init visible

    // phase 1: packed winner max (y major, tid minor)
    if (cell >= 0) atomicMax(&win[cell], (ye << 8) | tid);
    __syncthreads();

    // phase 2: losers tied at winning voxel -> extras list + bitmap bit (rare)
    int myslot = -1, myent = 0;
    if (cell >= 0) {
        const int w = win[cell];
        if ((w >> 8) == ye && (w & 255) != tid) {
            myslot = atomicAdd(&sdup, 1);
            myent  = (cell << 8) | tid;
            atomicOr(&sbm[cell >> 5], 1u << (cell & 31));
        }
    }
    __syncthreads();

    // write scratch (coalesced)
    *reinterpret_cast<int4*>(&g_win[b * NCELLS + cl4]) =
        *reinterpret_cast<const int4*>(&win[cl4]);
    if (tid < NBMW) g_bitmap[b * NBMW + tid] = sbm[tid];
    if (myslot >= 0 && myslot < MAXEXTRA)
        g_extras[b * MAXEXTRA + myslot] = myent;
    if (tid == 0) g_ecnt[b] = sdup;
}

// ---------------- Kernel B: 2 tiles/block, all loads front-batched ----------------
__global__ __launch_bounds__(256)
void stream_kernel(const float* __restrict__ features,   // (64,128,256)
                   float* __restrict__ out)              // (64,128,32,32)
{
    __shared__ __align__(16) float sf[2][CH_PER * NPTS];   // 2 x 8KB staging

    const int tid = threadIdx.x;
    const int cl4 = tid * 4;

    const int t0 = blockIdx.x;             // tile 0
    const int t1 = blockIdx.x + NBLOCKB;   // tile 1
    const int b0 = t0 >> 4, g0 = t0 & 15;
    const int b1 = t1 >> 4, g1 = t1 & 15;

    // --- front-batch ALL independent loads (max MLP, one latency wall) ---
    const int4 w40 = *reinterpret_cast<const int4*>(&g_win[b0 * NCELLS + cl4]);
    const int4 w41 = *reinterpret_cast<const int4*>(&g_win[b1 * NCELLS + cl4]);
    const unsigned bm0 = g_bitmap[b0 * NBMW + (cl4 >> 5)];
    const unsigned bm1 = g_bitmap[b1 * NBMW + (cl4 >> 5)];

    const float* __restrict__ fb0 = features + (size_t)(b0 * NCH + g0 * CH_PER) * NPTS;
    const float* __restrict__ fb1 = features + (size_t)(b1 * NCH + g1 * CH_PER) * NPTS;
    {
        const float4* __restrict__ s0 = reinterpret_cast<const float4*>(fb0);
        const float4* __restrict__ s1 = reinterpret_cast<const float4*>(fb1);
        float4* d0 = reinterpret_cast<float4*>(sf[0]);
        float4* d1 = reinterpret_cast<float4*>(sf[1]);
        #pragma unroll
        for (int i = 0; i < (CH_PER * NPTS / 4) / 256; i++) {   // 2 iters each
            d0[tid + i * 256] = s0[tid + i * 256];
            d1[tid + i * 256] = s1[tid + i * 256];
        }
    }
    __syncthreads();   // single barrier for both tiles

    // --- epilogue for each tile ---
    #pragma unroll
    for (int t = 0; t < 2; t++) {
        const int4     w4  = t ? w41 : w40;
        const unsigned bmw = t ? bm1 : bm0;
        const int      bb  = t ? b1  : b0;
        const int      gg  = t ? g1  : g0;
        const float* __restrict__ sft = sf[t];

        const int f0 = (w4.x < 0) ? -1 : (w4.x & 255);
        const int f1 = (w4.y < 0) ? -1 : (w4.y & 255);
        const int f2 = (w4.z < 0) ? -1 : (w4.z & 255);
        const int f3 = (w4.w < 0) ? -1 : (w4.w & 255);
        const bool hasextra = (bmw >> (cl4 & 31)) & 0xF;

        float* __restrict__ ob = out + (size_t)(bb * NCH + gg * CH_PER) * NCELLS + cl4;

        if (!hasextra) {
            // common path: predicated smem gathers + streaming STG.128
            #pragma unroll
            for (int c = 0; c < CH_PER; c++) {
                const float* __restrict__ frow = sft + c * NPTS;
                float4 v = make_float4(0.f, 0.f, 0.f, 0.f);
                if (f0 >= 0) v.x = frow[f0];
                if (f1 >= 0) v.y = frow[f1];
                if (f2 >= 0) v.z = frow[f2];
                if (f3 >= 0) v.w = frow[f3];
                __stcs(reinterpret_cast<float4*>(ob + c * NCELLS), v);
            }
        } else {
            // rare threads owning a multi-contributor cell
            const int ne = g_ecnt[bb];
            #pragma unroll 4
            for (int c = 0; c < CH_PER; c++) {
                const float* __restrict__ frow = sft + c * NPTS;
                float4 v = make_float4(0.f, 0.f, 0.f, 0.f);
                if (f0 >= 0) v.x = frow[f0];
                if (f1 >= 0) v.y = frow[f1];
                if (f2 >= 0) v.z = frow[f2];
                if (f3 >= 0) v.w = frow[f3];
                for (int k = 0; k < ne; k++) {
                    const int e  = g_extras[bb * MAXEXTRA + k];
                    const int dc = e >> 8;
                    const int dt = e & 255;
                    if      (dc == cl4    ) v.x += frow[dt];
                    else if (dc == cl4 + 1) v.y += frow[dt];
                    else if (dc == cl4 + 2) v.z += frow[dt];
                    else if (dc == cl4 + 3) v.w += frow[dt];
                }
                __stcs(reinterpret_cast<float4*>(ob + c * NCELLS), v);
            }
        }
    }
}

extern "C" void kernel_launch(void* const* d_in, const int* in_sizes, int n_in,
                              void* d_out, int out_size)
{
    const float* features = (const float*)d_in[0];   // 64*128*16*16
    const float* depth    = (const float*)d_in[1];   // 64*1*16*16
    const float* cam      = (const float*)d_in[2];   // 3*256
    float*       out      = (float*)d_out;           // 64*128*32*32

    winner_kernel<<<NBATCH, 256>>>(depth, cam);
    stream_kernel<<<NBLOCKB, 256>>>(features, out);
}